// round 1
// baseline (speedup 1.0000x reference)
#include <cuda_runtime.h>
#include <math.h>

#define D_MODEL 1024
#define N_HEADS 16
#define DK      64
#define BB      4
#define SS      2048
#define M_TOT   (BB*SS)   // 8192

// Scratch (static device arrays; no allocation allowed)
__device__ float g_Q[(size_t)BB*N_HEADS*SS*DK];
__device__ float g_K[(size_t)BB*N_HEADS*SS*DK];
__device__ float g_V[(size_t)BB*N_HEADS*SS*DK];
__device__ float g_O[(size_t)M_TOT*D_MODEL];

// ---------------------------------------------------------------------------
// GEMM: C = A @ B^T   (A: [M,1024] row-major, Bw: [N,1024] row-major)
// mode 0: C[m*1024+n]
// mode 1: scatter into [b,h,s,d] layout: m=b*2048+s, n=h*64+d
// ---------------------------------------------------------------------------
#define BM 128
#define BN 128
#define BK 16

__global__ __launch_bounds__(256) void gemm_nt(const float* __restrict__ A,
                                               const float* __restrict__ Bw,
                                               float* __restrict__ C,
                                               int mode) {
    __shared__ float As[BK][BM + 4];
    __shared__ float Bs[BK][BN + 4];

    const int K = 1024;
    int tid  = threadIdx.x;
    int tx   = tid & 15;       // 0..15  (n direction)
    int ty   = tid >> 4;       // 0..15  (m direction)
    int lrow = tid >> 2;       // 0..63
    int lcol = (tid & 3) << 2; // 0,4,8,12

    const float* Ap = A  + ((size_t)(blockIdx.y * BM + lrow)) * K + lcol;
    const float* Bp = Bw + ((size_t)(blockIdx.x * BN + lrow)) * K + lcol;

    float acc[8][8];
#pragma unroll
    for (int i = 0; i < 8; i++)
#pragma unroll
        for (int j = 0; j < 8; j++) acc[i][j] = 0.f;

    for (int k0 = 0; k0 < K; k0 += BK) {
        float4 a0 = *(const float4*)(Ap + k0);
        float4 a1 = *(const float4*)(Ap + (size_t)64 * K + k0);
        float4 b0 = *(const float4*)(Bp + k0);
        float4 b1 = *(const float4*)(Bp + (size_t)64 * K + k0);

        As[lcol + 0][lrow]      = a0.x;
        As[lcol + 1][lrow]      = a0.y;
        As[lcol + 2][lrow]      = a0.z;
        As[lcol + 3][lrow]      = a0.w;
        As[lcol + 0][lrow + 64] = a1.x;
        As[lcol + 1][lrow + 64] = a1.y;
        As[lcol + 2][lrow + 64] = a1.z;
        As[lcol + 3][lrow + 64] = a1.w;

        Bs[lcol + 0][lrow]      = b0.x;
        Bs[lcol + 1][lrow]      = b0.y;
        Bs[lcol + 2][lrow]      = b0.z;
        Bs[lcol + 3][lrow]      = b0.w;
        Bs[lcol + 0][lrow + 64] = b1.x;
        Bs[lcol + 1][lrow + 64] = b1.y;
        Bs[lcol + 2][lrow + 64] = b1.z;
        Bs[lcol + 3][lrow + 64] = b1.w;

        __syncthreads();

#pragma unroll
        for (int kk = 0; kk < BK; kk++) {
            float af[8], bf[8];
#pragma unroll
            for (int i = 0; i < 8; i++) af[i] = As[kk][ty * 8 + i];
#pragma unroll
            for (int i = 0; i < 8; i++) bf[i] = Bs[kk][tx * 8 + i];
#pragma unroll
            for (int i = 0; i < 8; i++)
#pragma unroll
                for (int j = 0; j < 8; j++)
                    acc[i][j] = fmaf(af[i], bf[j], acc[i][j]);
        }
        __syncthreads();
    }

#pragma unroll
    for (int i = 0; i < 8; i++) {
        int m = blockIdx.y * BM + ty * 8 + i;
#pragma unroll
        for (int j = 0; j < 8; j++) {
            int n = blockIdx.x * BN + tx * 8 + j;
            float v = acc[i][j];
            if (mode == 0) {
                C[(size_t)m * 1024 + n] = v;
            } else {
                int bb = m >> 11, s = m & 2047;
                int hh = n >> 6,  d = n & 63;
                C[(((size_t)(bb * N_HEADS + hh)) * SS + s) * DK + d] = v;
            }
        }
    }
}

// ---------------------------------------------------------------------------
// RoPE in-place on Q and K ([b,h,s,d] layout). One thread per (bh,s,pair).
// ---------------------------------------------------------------------------
__global__ void rope_kernel(float* __restrict__ Q, float* __restrict__ Kt,
                            const int* __restrict__ pos) {
    int idx = blockIdx.x * blockDim.x + threadIdx.x; // < 4*16*2048*32
    int i  = idx & 31;
    int s  = (idx >> 5) & (SS - 1);
    int bh = idx >> 16;

    double freq = exp2(-(2.0 * (double)i / 64.0) * 13.28771237954945); // log2(1e4)
    double ang  = (double)pos[s] * freq;
    double cd, sd;
    sincos(ang, &sd, &cd);
    float c = (float)cd, sn = (float)sd;

    size_t base = (((size_t)bh * SS) + s) * DK + 2 * i;

    float q1 = Q[base], q2 = Q[base + 1];
    Q[base]     = q1 * c - q2 * sn;
    Q[base + 1] = q1 * sn + q2 * c;

    float k1 = Kt[base], k2 = Kt[base + 1];
    Kt[base]     = k1 * c - k2 * sn;
    Kt[base + 1] = k1 * sn + k2 * c;
}

// ---------------------------------------------------------------------------
// Causal flash attention, fp32. One block per (q-tile of 64, head, batch).
// 64 threads; each thread owns one q row: q[64] and o[64] in registers.
// Writes output directly in [b,s, h*64+d] layout for the final GEMM.
// ---------------------------------------------------------------------------
__global__ __launch_bounds__(64) void attn_kernel(const float* __restrict__ Q,
                                                  const float* __restrict__ Kg,
                                                  const float* __restrict__ Vg,
                                                  float* __restrict__ O) {
    __shared__ float Ksm[64 * 64];
    __shared__ float Vsm[64 * 64];
    __shared__ float Ssm[64 * 64]; // [j][tid] -> conflict-free

    int qt = blockIdx.x, h = blockIdx.y, b = blockIdx.z;
    int tid = threadIdx.x;
    size_t hoff = ((size_t)(b * N_HEADS + h)) * SS * DK;
    int row = qt * 64 + tid;

    float q[64];
    {
        const float4* qp = (const float4*)(Q + hoff + (size_t)row * DK);
#pragma unroll
        for (int i = 0; i < 16; i++) {
            float4 v = qp[i];
            q[4 * i] = v.x; q[4 * i + 1] = v.y; q[4 * i + 2] = v.z; q[4 * i + 3] = v.w;
        }
    }

    float o[64];
#pragma unroll
    for (int d = 0; d < 64; d++) o[d] = 0.f;
    float mval = -1e30f;
    float l = 0.f;
    const float scale = 0.125f; // 1/sqrt(64)

    for (int kt = 0; kt <= qt; ++kt) {
        const float4* kp = (const float4*)(Kg + hoff + (size_t)kt * 64 * DK);
        const float4* vp = (const float4*)(Vg + hoff + (size_t)kt * 64 * DK);
        float4* ks4 = (float4*)Ksm;
        float4* vs4 = (float4*)Vsm;
#pragma unroll
        for (int i = 0; i < 16; i++) {
            ks4[i * 64 + tid] = kp[i * 64 + tid];
            vs4[i * 64 + tid] = vp[i * 64 + tid];
        }
        __syncthreads();

        int jlim = row - kt * 64; // j > jlim masked (only matters on diag tile)
        float tmax = -1e30f;
        for (int j = 0; j < 64; j++) {
            const float* kr = Ksm + j * 64;
            float acc = 0.f;
#pragma unroll
            for (int d = 0; d < 64; d++) acc = fmaf(q[d], kr[d], acc);
            float sc = (j <= jlim) ? acc * scale : -1e30f;
            Ssm[j * 64 + tid] = sc;
            tmax = fmaxf(tmax, sc);
        }

        float newm = fmaxf(mval, tmax);
        float corr = __expf(mval - newm);
        l *= corr;
#pragma unroll
        for (int d = 0; d < 64; d++) o[d] *= corr;

        for (int j = 0; j < 64; j++) {
            float p = __expf(Ssm[j * 64 + tid] - newm);
            l += p;
            const float* vr = Vsm + j * 64;
#pragma unroll
            for (int d = 0; d < 64; d++) o[d] = fmaf(p, vr[d], o[d]);
        }
        mval = newm;
        __syncthreads();
    }

    float inv = 1.f / l;
    float* op = O + ((size_t)(b * SS + row)) * D_MODEL + h * DK;
#pragma unroll
    for (int d = 0; d < 64; d += 4) {
        float4 v = make_float4(o[d] * inv, o[d + 1] * inv, o[d + 2] * inv, o[d + 3] * inv);
        *(float4*)(op + d) = v;
    }
}

// ---------------------------------------------------------------------------
extern "C" void kernel_launch(void* const* d_in, const int* in_sizes, int n_in,
                              void* d_out, int out_size) {
    const float* x   = (const float*)d_in[0];
    const int*   pos = (const int*)d_in[1];
    const float* WQ  = (const float*)d_in[2];
    const float* WK  = (const float*)d_in[3];
    const float* WV  = (const float*)d_in[4];
    const float* WO  = (const float*)d_in[5];
    float* out = (float*)d_out;

    float *Qb, *Kb, *Vb, *Ob;
    cudaGetSymbolAddress((void**)&Qb, g_Q);
    cudaGetSymbolAddress((void**)&Kb, g_K);
    cudaGetSymbolAddress((void**)&Vb, g_V);
    cudaGetSymbolAddress((void**)&Ob, g_O);

    dim3 ggrid(D_MODEL / BN, M_TOT / BM); // (8, 64)

    gemm_nt<<<ggrid, 256>>>(x, WQ, Qb, 1);
    gemm_nt<<<ggrid, 256>>>(x, WK, Kb, 1);
    gemm_nt<<<ggrid, 256>>>(x, WV, Vb, 1);

    int rope_threads = BB * N_HEADS * SS * 32; // 4,194,304
    rope_kernel<<<rope_threads / 256, 256>>>(Qb, Kb, pos);

    attn_kernel<<<dim3(SS / 64, N_HEADS, BB), 64>>>(Qb, Kb, Vb, Ob);

    gemm_nt<<<ggrid, 256>>>(Ob, WO, out, 0);
}

// round 2
// speedup vs baseline: 1.8710x; 1.8710x over previous
#include <cuda_runtime.h>
#include <math.h>

#define D_MODEL 1024
#define N_HEADS 16
#define DK      64
#define BB      4
#define SS      2048
#define M_TOT   (BB*SS)   // 8192

// Scratch (static device arrays; no allocation allowed)
__device__ float g_Q[(size_t)BB*N_HEADS*SS*DK];
__device__ float g_K[(size_t)BB*N_HEADS*SS*DK];
__device__ float g_V[(size_t)BB*N_HEADS*SS*DK];
__device__ float g_O[(size_t)M_TOT*D_MODEL];

// ---------------------------------------------------------------------------
// GEMM: C = A @ B^T   (A: [M,1024] row-major, Bw: [N,1024] row-major)
// Double-buffered smem pipeline, 1 sync per k-tile.
// mode 0: C[m*1024+n]
// mode 1: scatter into [b,h,s,d] layout: m=b*2048+s, n=h*64+d
// ---------------------------------------------------------------------------
#define BM 128
#define BN 128
#define BK 16

__device__ __forceinline__ void stage_store(float (*As)[BM + 4], float (*Bs)[BN + 4],
                                            int lrow, int lcol,
                                            float4 a0, float4 a1, float4 b0, float4 b1) {
    As[lcol + 0][lrow]      = a0.x;
    As[lcol + 1][lrow]      = a0.y;
    As[lcol + 2][lrow]      = a0.z;
    As[lcol + 3][lrow]      = a0.w;
    As[lcol + 0][lrow + 64] = a1.x;
    As[lcol + 1][lrow + 64] = a1.y;
    As[lcol + 2][lrow + 64] = a1.z;
    As[lcol + 3][lrow + 64] = a1.w;

    Bs[lcol + 0][lrow]      = b0.x;
    Bs[lcol + 1][lrow]      = b0.y;
    Bs[lcol + 2][lrow]      = b0.z;
    Bs[lcol + 3][lrow]      = b0.w;
    Bs[lcol + 0][lrow + 64] = b1.x;
    Bs[lcol + 1][lrow + 64] = b1.y;
    Bs[lcol + 2][lrow + 64] = b1.z;
    Bs[lcol + 3][lrow + 64] = b1.w;
}

__global__ __launch_bounds__(256) void gemm_nt(const float* __restrict__ A,
                                               const float* __restrict__ Bw,
                                               float* __restrict__ C,
                                               int mode) {
    __shared__ float As[2][BK][BM + 4];
    __shared__ float Bs[2][BK][BN + 4];

    const int K = 1024;
    int tid  = threadIdx.x;
    int tx   = tid & 15;       // 0..15  (n direction)
    int ty   = tid >> 4;       // 0..15  (m direction)
    int lrow = tid >> 2;       // 0..63
    int lcol = (tid & 3) << 2; // 0,4,8,12

    const float* Ap = A  + ((size_t)(blockIdx.y * BM + lrow)) * K + lcol;
    const float* Bp = Bw + ((size_t)(blockIdx.x * BN + lrow)) * K + lcol;

    float acc[8][8];
#pragma unroll
    for (int i = 0; i < 8; i++)
#pragma unroll
        for (int j = 0; j < 8; j++) acc[i][j] = 0.f;

    // Prologue: tile 0 into buffer 0
    {
        float4 a0 = *(const float4*)(Ap);
        float4 a1 = *(const float4*)(Ap + (size_t)64 * K);
        float4 b0 = *(const float4*)(Bp);
        float4 b1 = *(const float4*)(Bp + (size_t)64 * K);
        stage_store(As[0], Bs[0], lrow, lcol, a0, a1, b0, b1);
    }
    __syncthreads();

    int buf = 0;
    for (int k0 = 0; k0 < K; k0 += BK) {
        float4 a0, a1, b0, b1;
        bool more = (k0 + BK) < K;
        if (more) {
            a0 = *(const float4*)(Ap + k0 + BK);
            a1 = *(const float4*)(Ap + (size_t)64 * K + k0 + BK);
            b0 = *(const float4*)(Bp + k0 + BK);
            b1 = *(const float4*)(Bp + (size_t)64 * K + k0 + BK);
        }

#pragma unroll
        for (int kk = 0; kk < BK; kk++) {
            float af[8], bf[8];
#pragma unroll
            for (int i = 0; i < 8; i++) af[i] = As[buf][kk][ty * 8 + i];
#pragma unroll
            for (int i = 0; i < 8; i++) bf[i] = Bs[buf][kk][tx * 8 + i];
#pragma unroll
            for (int i = 0; i < 8; i++)
#pragma unroll
                for (int j = 0; j < 8; j++)
                    acc[i][j] = fmaf(af[i], bf[j], acc[i][j]);
        }

        if (more) {
            stage_store(As[buf ^ 1], Bs[buf ^ 1], lrow, lcol, a0, a1, b0, b1);
            __syncthreads();
            buf ^= 1;
        }
    }

#pragma unroll
    for (int i = 0; i < 8; i++) {
        int m = blockIdx.y * BM + ty * 8 + i;
#pragma unroll
        for (int j = 0; j < 8; j++) {
            int n = blockIdx.x * BN + tx * 8 + j;
            float v = acc[i][j];
            if (mode == 0) {
                C[(size_t)m * 1024 + n] = v;
            } else {
                int bb = m >> 11, s = m & 2047;
                int hh = n >> 6,  d = n & 63;
                C[(((size_t)(bb * N_HEADS + hh)) * SS + s) * DK + d] = v;
            }
        }
    }
}

// ---------------------------------------------------------------------------
// RoPE in-place on Q and K ([b,h,s,d] layout). Pure fp32. One thread per
// (bh, s, pair). sincosf (accurate range reduction) keeps error ~1 ulp.
// ---------------------------------------------------------------------------
__global__ __launch_bounds__(256) void rope_kernel(float* __restrict__ Q,
                                                   float* __restrict__ Kt,
                                                   const int* __restrict__ pos) {
    int idx = blockIdx.x * blockDim.x + threadIdx.x; // < 4*16*2048*32
    int i  = idx & 31;
    int s  = (idx >> 5) & (SS - 1);
    int bh = idx >> 16;

    // theta^(-2i/64) = 2^(-i * log2(theta)/32)
    float inv_freq = exp2f(-(float)i * (13.287712379549449f / 32.0f));
    float ang = (float)pos[s] * inv_freq;
    float c, sn;
    sincosf(ang, &sn, &c);

    size_t base = (((size_t)bh * SS) + s) * DK + 2 * i;

    float2 qv = *(float2*)(Q + base);
    float2 kv = *(float2*)(Kt + base);

    float2 qo = make_float2(qv.x * c - qv.y * sn, qv.x * sn + qv.y * c);
    float2 ko = make_float2(kv.x * c - kv.y * sn, kv.x * sn + kv.y * c);

    *(float2*)(Q + base)  = qo;
    *(float2*)(Kt + base) = ko;
}

// ---------------------------------------------------------------------------
// Causal flash attention, fp32. One block per (q-tile of 128, head, batch).
// 128 threads; each thread owns one q row: q[64] and o[64] in registers.
// K/V tiles of 64 rows staged in smem. Dynamic smem: 64KB.
// Writes output directly in [b,s, h*64+d] layout for the final GEMM.
// ---------------------------------------------------------------------------
#define BQ 128
#define BKT 64

extern __shared__ float attn_smem[];

__global__ __launch_bounds__(BQ) void attn_kernel(const float* __restrict__ Q,
                                                  const float* __restrict__ Kg,
                                                  const float* __restrict__ Vg,
                                                  float* __restrict__ O) {
    float* Ksm = attn_smem;              // 64*64
    float* Vsm = attn_smem + 4096;       // 64*64
    float* Ssm = attn_smem + 8192;       // [j][tid] = 64*128

    int qt = blockIdx.x, h = blockIdx.y, b = blockIdx.z;
    int tid = threadIdx.x;
    size_t hoff = ((size_t)(b * N_HEADS + h)) * SS * DK;
    int row = qt * BQ + tid;

    float q[64];
    {
        const float4* qp = (const float4*)(Q + hoff + (size_t)row * DK);
#pragma unroll
        for (int i = 0; i < 16; i++) {
            float4 v = qp[i];
            // fold softmax scale (1/8) into q
            q[4 * i]     = v.x * 0.125f;
            q[4 * i + 1] = v.y * 0.125f;
            q[4 * i + 2] = v.z * 0.125f;
            q[4 * i + 3] = v.w * 0.125f;
        }
    }

    float o[64];
#pragma unroll
    for (int d = 0; d < 64; d++) o[d] = 0.f;
    float mval = -1e30f;
    float l = 0.f;

    int ktmax = qt * 2 + 1; // last k-tile index touching this q block

    for (int kt = 0; kt <= ktmax; ++kt) {
        // Stage K/V tile (64x64) -> 1024 float4, 128 threads -> 8 each
        {
            const float4* kp = (const float4*)(Kg + hoff + (size_t)kt * BKT * DK);
            const float4* vp = (const float4*)(Vg + hoff + (size_t)kt * BKT * DK);
            float4* ks4 = (float4*)Ksm;
            float4* vs4 = (float4*)Vsm;
#pragma unroll
            for (int i = 0; i < 8; i++) {
                ks4[i * 128 + tid] = kp[i * 128 + tid];
                vs4[i * 128 + tid] = vp[i * 128 + tid];
            }
        }
        __syncthreads();

        int jlim = row - kt * BKT; // j > jlim masked
        bool active = (jlim >= 0);

        if (active) {
            bool full = (jlim >= 63);
            float tmax = -1e30f;
#pragma unroll 2
            for (int j = 0; j < 64; j++) {
                const float* kr = Ksm + j * 64;
                float acc = 0.f;
#pragma unroll
                for (int d = 0; d < 64; d++) acc = fmaf(q[d], kr[d], acc);
                float sc = (full || j <= jlim) ? acc : -1e30f;
                Ssm[j * 128 + tid] = sc;
                tmax = fmaxf(tmax, sc);
            }

            float newm = fmaxf(mval, tmax);
            float corr = __expf(mval - newm);
            l *= corr;
#pragma unroll
            for (int d = 0; d < 64; d++) o[d] *= corr;

#pragma unroll 2
            for (int j = 0; j < 64; j++) {
                float p = __expf(Ssm[j * 128 + tid] - newm);
                l += p;
                const float* vr = Vsm + j * 64;
#pragma unroll
                for (int d = 0; d < 64; d++) o[d] = fmaf(p, vr[d], o[d]);
            }
            mval = newm;
        }
        __syncthreads();
    }

    float inv = 1.f / l;
    float* op = O + ((size_t)(b * SS + row)) * D_MODEL + h * DK;
#pragma unroll
    for (int d = 0; d < 64; d += 4) {
        float4 v = make_float4(o[d] * inv, o[d + 1] * inv, o[d + 2] * inv, o[d + 3] * inv);
        *(float4*)(op + d) = v;
    }
}

// ---------------------------------------------------------------------------
extern "C" void kernel_launch(void* const* d_in, const int* in_sizes, int n_in,
                              void* d_out, int out_size) {
    const float* x   = (const float*)d_in[0];
    const int*   pos = (const int*)d_in[1];
    const float* WQ  = (const float*)d_in[2];
    const float* WK  = (const float*)d_in[3];
    const float* WV  = (const float*)d_in[4];
    const float* WO  = (const float*)d_in[5];
    float* out = (float*)d_out;

    float *Qb, *Kb, *Vb, *Ob;
    cudaGetSymbolAddress((void**)&Qb, g_Q);
    cudaGetSymbolAddress((void**)&Kb, g_K);
    cudaGetSymbolAddress((void**)&Vb, g_V);
    cudaGetSymbolAddress((void**)&Ob, g_O);

    dim3 ggrid(D_MODEL / BN, M_TOT / BM); // (8, 64)

    gemm_nt<<<ggrid, 256>>>(x, WQ, Qb, 1);
    gemm_nt<<<ggrid, 256>>>(x, WK, Kb, 1);
    gemm_nt<<<ggrid, 256>>>(x, WV, Vb, 1);

    int rope_threads = BB * N_HEADS * SS * 32; // 4,194,304
    rope_kernel<<<rope_threads / 256, 256>>>(Qb, Kb, pos);

    int attn_smem_bytes = (4096 + 4096 + 64 * 128) * sizeof(float); // 64KB
    cudaFuncSetAttribute(attn_kernel, cudaFuncAttributeMaxDynamicSharedMemorySize,
                         attn_smem_bytes);
    attn_kernel<<<dim3(SS / BQ, N_HEADS, BB), BQ, attn_smem_bytes>>>(Qb, Kb, Vb, Ob);

    gemm_nt<<<ggrid, 256>>>(Ob, WO, out, 0);
}

// round 4
// speedup vs baseline: 2.7170x; 1.4522x over previous
#include <cuda_runtime.h>
#include <cuda_bf16.h>
#include <math.h>
#include <stdint.h>

#define D_MODEL 1024
#define N_HEADS 16
#define DK      64
#define BB      4
#define SS      2048
#define M_TOT   (BB*SS)   // 8192

// Scratch (static device arrays; no allocation allowed)
__device__ float g_Q[(size_t)BB*N_HEADS*SS*DK];
__device__ float g_K[(size_t)BB*N_HEADS*SS*DK];
__device__ float g_V[(size_t)BB*N_HEADS*SS*DK];
__device__ float g_O[(size_t)M_TOT*D_MODEL];
// bf16 hi/lo split buffers: [kb][row][hi 32bf16 | lo 32bf16] = 128B per row
__device__ char  g_xc[(size_t)32*M_TOT*128];    // 32MB (activations)
__device__ char  g_wc[(size_t)32*1024*128];     // 4MB  (weights)

extern __shared__ char dsm[];

// ---------------------------------------------------------------------------
// PTX helpers (arch-agnostic: sm_80+ features only — target is plain sm_103)
// ---------------------------------------------------------------------------
__device__ __forceinline__ uint32_t smem_u32(const void* p) {
    uint32_t a;
    asm("{ .reg .u64 t; cvta.to.shared.u64 t, %1; cvt.u32.u64 %0, t; }"
        : "=r"(a) : "l"(p));
    return a;
}

#define CP16(dst, src) \
    asm volatile("cp.async.cg.shared.global [%0], [%1], 16;" :: "r"(dst), "l"(src))
#define CPCOMMIT() asm volatile("cp.async.commit_group;" ::: "memory")
#define CPWAIT0()  asm volatile("cp.async.wait_group 0;" ::: "memory")

__device__ __forceinline__ void ldsm4(uint32_t* r, uint32_t addr) {
    asm volatile("ldmatrix.sync.aligned.m8n8.x4.shared.b16 {%0,%1,%2,%3}, [%4];"
        : "=r"(r[0]), "=r"(r[1]), "=r"(r[2]), "=r"(r[3]) : "r"(addr));
}

__device__ __forceinline__ void mma_bf16(float* d, const uint32_t* a,
                                         uint32_t b0, uint32_t b1) {
    asm volatile(
        "mma.sync.aligned.m16n8k16.row.col.f32.bf16.bf16.f32 "
        "{%0,%1,%2,%3}, {%4,%5,%6,%7}, {%8,%9}, {%0,%1,%2,%3};"
        : "+f"(d[0]), "+f"(d[1]), "+f"(d[2]), "+f"(d[3])
        : "r"(a[0]), "r"(a[1]), "r"(a[2]), "r"(a[3]), "r"(b0), "r"(b1));
}

__device__ __forceinline__ uint32_t pack_bf2(__nv_bfloat16 a, __nv_bfloat16 b) {
    return (uint32_t)__bfloat16_as_ushort(a) |
           ((uint32_t)__bfloat16_as_ushort(b) << 16);
}

// ---------------------------------------------------------------------------
// Convert fp32 [M][1024] into split-bf16 layout:
// dst byte offset ((kb*M + m) * 128): [hi: 32 bf16][lo: 32 bf16] for k = kb*32..+31
// ---------------------------------------------------------------------------
__global__ __launch_bounds__(256) void convert_split(const float* __restrict__ src,
                                                     char* __restrict__ dst,
                                                     int mshift) {
    int idx = blockIdx.x * blockDim.x + threadIdx.x;
    int M = 1 << mshift;
    int m  = idx & (M - 1);
    int kb = idx >> mshift;

    const float4* s4 = (const float4*)(src + (size_t)m * 1024 + kb * 32);
    uint32_t h[16], l[16];
#pragma unroll
    for (int i = 0; i < 8; i++) {
        float4 v = s4[i];
        __nv_bfloat16 h0 = __float2bfloat16(v.x);
        __nv_bfloat16 h1 = __float2bfloat16(v.y);
        __nv_bfloat16 h2 = __float2bfloat16(v.z);
        __nv_bfloat16 h3 = __float2bfloat16(v.w);
        __nv_bfloat16 l0 = __float2bfloat16(v.x - __bfloat162float(h0));
        __nv_bfloat16 l1 = __float2bfloat16(v.y - __bfloat162float(h1));
        __nv_bfloat16 l2 = __float2bfloat16(v.z - __bfloat162float(h2));
        __nv_bfloat16 l3 = __float2bfloat16(v.w - __bfloat162float(h3));
        h[i * 2]     = pack_bf2(h0, h1);
        h[i * 2 + 1] = pack_bf2(h2, h3);
        l[i * 2]     = pack_bf2(l0, l1);
        l[i * 2 + 1] = pack_bf2(l2, l3);
    }
    uint4* d4 = (uint4*)(dst + ((size_t)kb * M + m) * 128);
#pragma unroll
    for (int i = 0; i < 4; i++)
        d4[i] = make_uint4(h[4 * i], h[4 * i + 1], h[4 * i + 2], h[4 * i + 3]);
#pragma unroll
    for (int i = 0; i < 4; i++)
        d4[4 + i] = make_uint4(l[4 * i], l[4 * i + 1], l[4 * i + 2], l[4 * i + 3]);
}

// ---------------------------------------------------------------------------
// HMMA GEMM: C = A @ W^T using bf16 hi/lo split (3 MMAs per tile-pair).
// A: split layout [kb][8192][128B]; W: split layout [kb][1024][128B].
// Block 128x128, 8 warps of 64x32. cp.async double-buffered, 32-K stages.
// mode 0: C[m*1024+n];  mode 1: scatter to [b,h,s,d].
// ---------------------------------------------------------------------------
#define NSTAGE 32

__global__ __launch_bounds__(256) void gemm_hmma(const char* __restrict__ Ag,
                                                 const char* __restrict__ Bg,
                                                 float* __restrict__ C,
                                                 int mode) {
    uint32_t sb = smem_u32(dsm);
    int tid = threadIdx.x;
    int wid = tid >> 5, lane = tid & 31;
    int wm = wid & 1, wn = wid >> 1;
    int m0 = blockIdx.y * 128, n0 = blockIdx.x * 128;

    float acc[4][4][4];
#pragma unroll
    for (int a = 0; a < 4; a++)
#pragma unroll
        for (int b = 0; b < 4; b++)
#pragma unroll
            for (int c = 0; c < 4; c++) acc[a][b][c] = 0.f;

    // stage copy: A rows m0..m0+127 and B rows n0..n0+127 of k-block kb
    // smem row: 128B = [hi 64B | lo 64B], chunk swizzle c' = c ^ (r&7)
#define STAGE_CP(kb, buf)                                                      \
    do {                                                                       \
        uint32_t abase = sb + (buf) * 32768;                                   \
        uint32_t bbase = abase + 16384;                                        \
        const char* ag = Ag + ((size_t)(kb) * M_TOT + m0) * 128;               \
        const char* bg = Bg + ((size_t)(kb) * 1024 + n0) * 128;                \
        _Pragma("unroll")                                                      \
        for (int i = 0; i < 4; i++) {                                          \
            int q = tid * 4 + i; int r = q >> 3, c = q & 7;                    \
            CP16(abase + r * 128 + ((c ^ (r & 7)) << 4), ag + r * 128 + c * 16); \
        }                                                                      \
        _Pragma("unroll")                                                      \
        for (int i = 0; i < 4; i++) {                                          \
            int q = tid * 4 + i; int r = q >> 3, c = q & 7;                    \
            CP16(bbase + r * 128 + ((c ^ (r & 7)) << 4), bg + r * 128 + c * 16); \
        }                                                                      \
    } while (0)

    STAGE_CP(0, 0);
    CPCOMMIT();
    CPWAIT0();
    __syncthreads();

    int r16 = lane & 15, hf = lane >> 4;

    for (int kb = 0; kb < NSTAGE; kb++) {
        int buf = kb & 1;
        if (kb + 1 < NSTAGE) {
            STAGE_CP(kb + 1, buf ^ 1);
            CPCOMMIT();
        }
        uint32_t abase = sb + buf * 32768;
        uint32_t bbase = abase + 16384;

#pragma unroll
        for (int s = 0; s < 2; s++) {
            uint32_t ah[4][4], al[4][4], bh[2][4], bl[2][4];
#pragma unroll
            for (int mt = 0; mt < 4; mt++) {
                int r = wm * 64 + mt * 16 + r16;
                int ch = s * 2 + hf;        // hi chunks 0..3
                int cl = 4 + s * 2 + hf;    // lo chunks 4..7
                ldsm4(ah[mt], abase + r * 128 + ((ch ^ (r & 7)) << 4));
                ldsm4(al[mt], abase + r * 128 + ((cl ^ (r & 7)) << 4));
            }
#pragma unroll
            for (int g = 0; g < 2; g++) {
                int r = wn * 32 + g * 16 + r16;
                int ch = s * 2 + hf;
                int cl = 4 + s * 2 + hf;
                ldsm4(bh[g], bbase + r * 128 + ((ch ^ (r & 7)) << 4));
                ldsm4(bl[g], bbase + r * 128 + ((cl ^ (r & 7)) << 4));
            }
#pragma unroll
            for (int mt = 0; mt < 4; mt++)
#pragma unroll
                for (int nt = 0; nt < 4; nt++) {
                    int g = nt >> 1, e = nt & 1;
                    mma_bf16(acc[mt][nt], ah[mt], bh[g][e], bh[g][e + 2]);
                    mma_bf16(acc[mt][nt], al[mt], bh[g][e], bh[g][e + 2]);
                    mma_bf16(acc[mt][nt], ah[mt], bl[g][e], bl[g][e + 2]);
                }
        }
        if (kb + 1 < NSTAGE) {
            CPWAIT0();
            __syncthreads();
        }
    }

    // Epilogue
    int r0 = lane >> 2, c0 = (lane & 3) * 2;
#pragma unroll
    for (int mt = 0; mt < 4; mt++) {
#pragma unroll
        for (int nt = 0; nt < 4; nt++) {
            int m = m0 + wm * 64 + mt * 16 + r0;
            int n = n0 + wn * 32 + nt * 8 + c0;
            float2 v01 = make_float2(acc[mt][nt][0], acc[mt][nt][1]);
            float2 v23 = make_float2(acc[mt][nt][2], acc[mt][nt][3]);
            if (mode == 0) {
                *(float2*)(C + (size_t)m * 1024 + n) = v01;
                *(float2*)(C + (size_t)(m + 8) * 1024 + n) = v23;
            } else {
                int hh = n >> 6, d = n & 63;
                {
                    int bb = m >> 11, sl = m & 2047;
                    *(float2*)(C + (((size_t)(bb * N_HEADS + hh)) * SS + sl) * DK + d) = v01;
                }
                {
                    int m8 = m + 8;
                    int bb = m8 >> 11, sl = m8 & 2047;
                    *(float2*)(C + (((size_t)(bb * N_HEADS + hh)) * SS + sl) * DK + d) = v23;
                }
            }
        }
    }
}

// ---------------------------------------------------------------------------
// RoPE in-place on Q and K ([b,h,s,d] layout). Pure fp32.
// ---------------------------------------------------------------------------
__global__ __launch_bounds__(256) void rope_kernel(float* __restrict__ Q,
                                                   float* __restrict__ Kt,
                                                   const int* __restrict__ pos) {
    int idx = blockIdx.x * blockDim.x + threadIdx.x;
    int i  = idx & 31;
    int s  = (idx >> 5) & (SS - 1);
    int bh = idx >> 16;

    float inv_freq = exp2f(-(float)i * (13.287712379549449f / 32.0f));
    float ang = (float)pos[s] * inv_freq;
    float c, sn;
    sincosf(ang, &sn, &c);

    size_t base = (((size_t)bh * SS) + s) * DK + 2 * i;

    float2 qv = *(float2*)(Q + base);
    float2 kv = *(float2*)(Kt + base);

    *(float2*)(Q + base)  = make_float2(qv.x * c - qv.y * sn, qv.x * sn + qv.y * c);
    *(float2*)(Kt + base) = make_float2(kv.x * c - kv.y * sn, kv.x * sn + kv.y * c);
}

// ---------------------------------------------------------------------------
// Causal flash attention, fp32 SIMT (round-2 version, unchanged).
// ---------------------------------------------------------------------------
#define BQ 128
#define BKT 64

__global__ __launch_bounds__(BQ) void attn_kernel(const float* __restrict__ Q,
                                                  const float* __restrict__ Kg,
                                                  const float* __restrict__ Vg,
                                                  float* __restrict__ O) {
    float* smf = (float*)dsm;
    float* Ksm = smf;            // 64*64
    float* Vsm = smf + 4096;     // 64*64
    float* Ssm = smf + 8192;     // [j][tid] = 64*128

    int qt = blockIdx.x, h = blockIdx.y, b = blockIdx.z;
    int tid = threadIdx.x;
    size_t hoff = ((size_t)(b * N_HEADS + h)) * SS * DK;
    int row = qt * BQ + tid;

    float q[64];
    {
        const float4* qp = (const float4*)(Q + hoff + (size_t)row * DK);
#pragma unroll
        for (int i = 0; i < 16; i++) {
            float4 v = qp[i];
            q[4 * i]     = v.x * 0.125f;
            q[4 * i + 1] = v.y * 0.125f;
            q[4 * i + 2] = v.z * 0.125f;
            q[4 * i + 3] = v.w * 0.125f;
        }
    }

    float o[64];
#pragma unroll
    for (int d = 0; d < 64; d++) o[d] = 0.f;
    float mval = -1e30f;
    float l = 0.f;

    int ktmax = qt * 2 + 1;

    for (int kt = 0; kt <= ktmax; ++kt) {
        {
            const float4* kp = (const float4*)(Kg + hoff + (size_t)kt * BKT * DK);
            const float4* vp = (const float4*)(Vg + hoff + (size_t)kt * BKT * DK);
            float4* ks4 = (float4*)Ksm;
            float4* vs4 = (float4*)Vsm;
#pragma unroll
            for (int i = 0; i < 8; i++) {
                ks4[i * 128 + tid] = kp[i * 128 + tid];
                vs4[i * 128 + tid] = vp[i * 128 + tid];
            }
        }
        __syncthreads();

        int jlim = row - kt * BKT;
        bool active = (jlim >= 0);

        if (active) {
            bool full = (jlim >= 63);
            float tmax = -1e30f;
#pragma unroll 2
            for (int j = 0; j < 64; j++) {
                const float* kr = Ksm + j * 64;
                float acc = 0.f;
#pragma unroll
                for (int d = 0; d < 64; d++) acc = fmaf(q[d], kr[d], acc);
                float sc = (full || j <= jlim) ? acc : -1e30f;
                Ssm[j * 128 + tid] = sc;
                tmax = fmaxf(tmax, sc);
            }

            float newm = fmaxf(mval, tmax);
            float corr = __expf(mval - newm);
            l *= corr;
#pragma unroll
            for (int d = 0; d < 64; d++) o[d] *= corr;

#pragma unroll 2
            for (int j = 0; j < 64; j++) {
                float p = __expf(Ssm[j * 128 + tid] - newm);
                l += p;
                const float* vr = Vsm + j * 64;
#pragma unroll
                for (int d = 0; d < 64; d++) o[d] = fmaf(p, vr[d], o[d]);
            }
            mval = newm;
        }
        __syncthreads();
    }

    float inv = 1.f / l;
    float* op = O + ((size_t)(b * SS + row)) * D_MODEL + h * DK;
#pragma unroll
    for (int d = 0; d < 64; d += 4) {
        float4 v = make_float4(o[d] * inv, o[d + 1] * inv, o[d + 2] * inv, o[d + 3] * inv);
        *(float4*)(op + d) = v;
    }
}

// ---------------------------------------------------------------------------
extern "C" void kernel_launch(void* const* d_in, const int* in_sizes, int n_in,
                              void* d_out, int out_size) {
    const float* x   = (const float*)d_in[0];
    const int*   pos = (const int*)d_in[1];
    const float* WQ  = (const float*)d_in[2];
    const float* WK  = (const float*)d_in[3];
    const float* WV  = (const float*)d_in[4];
    const float* WO  = (const float*)d_in[5];
    float* out = (float*)d_out;

    float *Qb, *Kb, *Vb, *Ob;
    char *xc, *wc;
    cudaGetSymbolAddress((void**)&Qb, g_Q);
    cudaGetSymbolAddress((void**)&Kb, g_K);
    cudaGetSymbolAddress((void**)&Vb, g_V);
    cudaGetSymbolAddress((void**)&Ob, g_O);
    cudaGetSymbolAddress((void**)&xc, g_xc);
    cudaGetSymbolAddress((void**)&wc, g_wc);

    cudaFuncSetAttribute(gemm_hmma, cudaFuncAttributeMaxDynamicSharedMemorySize, 65536);

    dim3 ggrid(D_MODEL / 128, M_TOT / 128); // (8, 64)

    // convert activations once, weights per GEMM
    convert_split<<<(M_TOT * 32) / 256, 256>>>(x, xc, 13);
    convert_split<<<(1024 * 32) / 256, 256>>>(WQ, wc, 10);
    gemm_hmma<<<ggrid, 256, 65536>>>(xc, wc, Qb, 1);
    convert_split<<<(1024 * 32) / 256, 256>>>(WK, wc, 10);
    gemm_hmma<<<ggrid, 256, 65536>>>(xc, wc, Kb, 1);
    convert_split<<<(1024 * 32) / 256, 256>>>(WV, wc, 10);
    gemm_hmma<<<ggrid, 256, 65536>>>(xc, wc, Vb, 1);

    int rope_threads = BB * N_HEADS * SS * 32;
    rope_kernel<<<rope_threads / 256, 256>>>(Qb, Kb, pos);

    int attn_smem_bytes = (4096 + 4096 + 64 * 128) * sizeof(float); // 64KB
    cudaFuncSetAttribute(attn_kernel, cudaFuncAttributeMaxDynamicSharedMemorySize,
                         attn_smem_bytes);
    attn_kernel<<<dim3(SS / BQ, N_HEADS, BB), BQ, attn_smem_bytes>>>(Qb, Kb, Vb, Ob);

    convert_split<<<(M_TOT * 32) / 256, 256>>>(Ob, xc, 13);
    convert_split<<<(1024 * 32) / 256, 256>>>(WO, wc, 10);
    gemm_hmma<<<ggrid, 256, 65536>>>(xc, wc, out, 0);
}

// round 5
// speedup vs baseline: 4.9982x; 1.8396x over previous
#include <cuda_runtime.h>
#include <cuda_bf16.h>
#include <math.h>
#include <stdint.h>

#define D_MODEL 1024
#define N_HEADS 16
#define DK      64
#define BB      4
#define SS      2048
#define M_TOT   (BB*SS)   // 8192

// Scratch (static device arrays; no allocation allowed)
__device__ float g_Q[(size_t)BB*N_HEADS*SS*DK];
__device__ float g_K[(size_t)BB*N_HEADS*SS*DK];
__device__ float g_V[(size_t)BB*N_HEADS*SS*DK];
__device__ float g_O[(size_t)M_TOT*D_MODEL];
// bf16 hi/lo split buffers for GEMM: [kb][row][hi 32bf16 | lo 32bf16]
__device__ char  g_xc[(size_t)32*M_TOT*128];    // 32MB (activations)
__device__ char  g_wc[(size_t)32*1024*128];     // 4MB  (weights)
// split-bf16 planes for attention: [b*16+h][s][64] bf16 (128B rows)
__device__ char  g_qh[(size_t)BB*N_HEADS*SS*DK*2];
__device__ char  g_ql[(size_t)BB*N_HEADS*SS*DK*2];
__device__ char  g_kh[(size_t)BB*N_HEADS*SS*DK*2];
__device__ char  g_kl[(size_t)BB*N_HEADS*SS*DK*2];
__device__ char  g_vh[(size_t)BB*N_HEADS*SS*DK*2];
__device__ char  g_vl[(size_t)BB*N_HEADS*SS*DK*2];

extern __shared__ char dsm[];

// ---------------------------------------------------------------------------
// PTX helpers (arch-agnostic: sm_80+ features only — target is plain sm_103)
// ---------------------------------------------------------------------------
__device__ __forceinline__ uint32_t smem_u32(const void* p) {
    uint32_t a;
    asm("{ .reg .u64 t; cvta.to.shared.u64 t, %1; cvt.u32.u64 %0, t; }"
        : "=r"(a) : "l"(p));
    return a;
}

#define CP16(dst, src) \
    asm volatile("cp.async.cg.shared.global [%0], [%1], 16;" :: "r"(dst), "l"(src))
#define CPCOMMIT() asm volatile("cp.async.commit_group;" ::: "memory")
#define CPWAIT0()  asm volatile("cp.async.wait_group 0;" ::: "memory")

__device__ __forceinline__ void ldsm4(uint32_t* r, uint32_t addr) {
    asm volatile("ldmatrix.sync.aligned.m8n8.x4.shared.b16 {%0,%1,%2,%3}, [%4];"
        : "=r"(r[0]), "=r"(r[1]), "=r"(r[2]), "=r"(r[3]) : "r"(addr));
}
__device__ __forceinline__ void ldsm4t(uint32_t* r, uint32_t addr) {
    asm volatile("ldmatrix.sync.aligned.m8n8.x4.trans.shared.b16 {%0,%1,%2,%3}, [%4];"
        : "=r"(r[0]), "=r"(r[1]), "=r"(r[2]), "=r"(r[3]) : "r"(addr));
}

__device__ __forceinline__ void mma_bf16(float* d, const uint32_t* a,
                                         uint32_t b0, uint32_t b1) {
    asm volatile(
        "mma.sync.aligned.m16n8k16.row.col.f32.bf16.bf16.f32 "
        "{%0,%1,%2,%3}, {%4,%5,%6,%7}, {%8,%9}, {%0,%1,%2,%3};"
        : "+f"(d[0]), "+f"(d[1]), "+f"(d[2]), "+f"(d[3])
        : "r"(a[0]), "r"(a[1]), "r"(a[2]), "r"(a[3]), "r"(b0), "r"(b1));
}

__device__ __forceinline__ uint32_t pack_bf2(__nv_bfloat16 a, __nv_bfloat16 b) {
    return (uint32_t)__bfloat16_as_ushort(a) |
           ((uint32_t)__bfloat16_as_ushort(b) << 16);
}

// ---------------------------------------------------------------------------
// Convert fp32 [M][1024] into split-bf16 GEMM layout.
// ---------------------------------------------------------------------------
__global__ __launch_bounds__(256) void convert_split(const float* __restrict__ src,
                                                     char* __restrict__ dst,
                                                     int mshift) {
    int idx = blockIdx.x * blockDim.x + threadIdx.x;
    int M = 1 << mshift;
    int m  = idx & (M - 1);
    int kb = idx >> mshift;

    const float4* s4 = (const float4*)(src + (size_t)m * 1024 + kb * 32);
    uint32_t h[16], l[16];
#pragma unroll
    for (int i = 0; i < 8; i++) {
        float4 v = s4[i];
        __nv_bfloat16 h0 = __float2bfloat16(v.x);
        __nv_bfloat16 h1 = __float2bfloat16(v.y);
        __nv_bfloat16 h2 = __float2bfloat16(v.z);
        __nv_bfloat16 h3 = __float2bfloat16(v.w);
        __nv_bfloat16 l0 = __float2bfloat16(v.x - __bfloat162float(h0));
        __nv_bfloat16 l1 = __float2bfloat16(v.y - __bfloat162float(h1));
        __nv_bfloat16 l2 = __float2bfloat16(v.z - __bfloat162float(h2));
        __nv_bfloat16 l3 = __float2bfloat16(v.w - __bfloat162float(h3));
        h[i * 2]     = pack_bf2(h0, h1);
        h[i * 2 + 1] = pack_bf2(h2, h3);
        l[i * 2]     = pack_bf2(l0, l1);
        l[i * 2 + 1] = pack_bf2(l2, l3);
    }
    uint4* d4 = (uint4*)(dst + ((size_t)kb * M + m) * 128);
#pragma unroll
    for (int i = 0; i < 4; i++)
        d4[i] = make_uint4(h[4 * i], h[4 * i + 1], h[4 * i + 2], h[4 * i + 3]);
#pragma unroll
    for (int i = 0; i < 4; i++)
        d4[4 + i] = make_uint4(l[4 * i], l[4 * i + 1], l[4 * i + 2], l[4 * i + 3]);
}

// ---------------------------------------------------------------------------
// HMMA GEMM (round-4, unchanged): C = A @ W^T via bf16 hi/lo split.
// ---------------------------------------------------------------------------
#define NSTAGE 32

__global__ __launch_bounds__(256) void gemm_hmma(const char* __restrict__ Ag,
                                                 const char* __restrict__ Bg,
                                                 float* __restrict__ C,
                                                 int mode) {
    uint32_t sb = smem_u32(dsm);
    int tid = threadIdx.x;
    int wid = tid >> 5, lane = tid & 31;
    int wm = wid & 1, wn = wid >> 1;
    int m0 = blockIdx.y * 128, n0 = blockIdx.x * 128;

    float acc[4][4][4];
#pragma unroll
    for (int a = 0; a < 4; a++)
#pragma unroll
        for (int b = 0; b < 4; b++)
#pragma unroll
            for (int c = 0; c < 4; c++) acc[a][b][c] = 0.f;

#define STAGE_CP(kb, buf)                                                      \
    do {                                                                       \
        uint32_t abase = sb + (buf) * 32768;                                   \
        uint32_t bbase = abase + 16384;                                        \
        const char* ag = Ag + ((size_t)(kb) * M_TOT + m0) * 128;               \
        const char* bg = Bg + ((size_t)(kb) * 1024 + n0) * 128;                \
        _Pragma("unroll")                                                      \
        for (int i = 0; i < 4; i++) {                                          \
            int q = tid * 4 + i; int r = q >> 3, c = q & 7;                    \
            CP16(abase + r * 128 + ((c ^ (r & 7)) << 4), ag + r * 128 + c * 16); \
        }                                                                      \
        _Pragma("unroll")                                                      \
        for (int i = 0; i < 4; i++) {                                          \
            int q = tid * 4 + i; int r = q >> 3, c = q & 7;                    \
            CP16(bbase + r * 128 + ((c ^ (r & 7)) << 4), bg + r * 128 + c * 16); \
        }                                                                      \
    } while (0)

    STAGE_CP(0, 0);
    CPCOMMIT();
    CPWAIT0();
    __syncthreads();

    int r16 = lane & 15, hf = lane >> 4;

    for (int kb = 0; kb < NSTAGE; kb++) {
        int buf = kb & 1;
        if (kb + 1 < NSTAGE) {
            STAGE_CP(kb + 1, buf ^ 1);
            CPCOMMIT();
        }
        uint32_t abase = sb + buf * 32768;
        uint32_t bbase = abase + 16384;

#pragma unroll
        for (int s = 0; s < 2; s++) {
            uint32_t ah[4][4], al[4][4], bh[2][4], bl[2][4];
#pragma unroll
            for (int mt = 0; mt < 4; mt++) {
                int r = wm * 64 + mt * 16 + r16;
                int ch = s * 2 + hf;
                int cl = 4 + s * 2 + hf;
                ldsm4(ah[mt], abase + r * 128 + ((ch ^ (r & 7)) << 4));
                ldsm4(al[mt], abase + r * 128 + ((cl ^ (r & 7)) << 4));
            }
#pragma unroll
            for (int g = 0; g < 2; g++) {
                int r = wn * 32 + g * 16 + r16;
                int ch = s * 2 + hf;
                int cl = 4 + s * 2 + hf;
                ldsm4(bh[g], bbase + r * 128 + ((ch ^ (r & 7)) << 4));
                ldsm4(bl[g], bbase + r * 128 + ((cl ^ (r & 7)) << 4));
            }
#pragma unroll
            for (int mt = 0; mt < 4; mt++)
#pragma unroll
                for (int nt = 0; nt < 4; nt++) {
                    int g = nt >> 1, e = nt & 1;
                    mma_bf16(acc[mt][nt], ah[mt], bh[g][e], bh[g][e + 2]);
                    mma_bf16(acc[mt][nt], al[mt], bh[g][e], bh[g][e + 2]);
                    mma_bf16(acc[mt][nt], ah[mt], bl[g][e], bl[g][e + 2]);
                }
        }
        if (kb + 1 < NSTAGE) {
            CPWAIT0();
            __syncthreads();
        }
    }

    int r0 = lane >> 2, c0 = (lane & 3) * 2;
#pragma unroll
    for (int mt = 0; mt < 4; mt++) {
#pragma unroll
        for (int nt = 0; nt < 4; nt++) {
            int m = m0 + wm * 64 + mt * 16 + r0;
            int n = n0 + wn * 32 + nt * 8 + c0;
            float2 v01 = make_float2(acc[mt][nt][0], acc[mt][nt][1]);
            float2 v23 = make_float2(acc[mt][nt][2], acc[mt][nt][3]);
            if (mode == 0) {
                *(float2*)(C + (size_t)m * 1024 + n) = v01;
                *(float2*)(C + (size_t)(m + 8) * 1024 + n) = v23;
            } else {
                int hh = n >> 6, d = n & 63;
                {
                    int bb = m >> 11, sl = m & 2047;
                    *(float2*)(C + (((size_t)(bb * N_HEADS + hh)) * SS + sl) * DK + d) = v01;
                }
                {
                    int m8 = m + 8;
                    int bb = m8 >> 11, sl = m8 & 2047;
                    *(float2*)(C + (((size_t)(bb * N_HEADS + hh)) * SS + sl) * DK + d) = v23;
                }
            }
        }
    }
}

// ---------------------------------------------------------------------------
// RoPE + split-bf16 conversion: reads fp32 Q/K [b,h,s,d], applies rope,
// folds 1/sqrt(d)=0.125 into Q (exact), writes hi/lo bf16 planes.
// ---------------------------------------------------------------------------
__global__ __launch_bounds__(256) void rope_split(const float* __restrict__ Q,
                                                  const float* __restrict__ K,
                                                  const int* __restrict__ pos,
                                                  char* __restrict__ qh,
                                                  char* __restrict__ ql,
                                                  char* __restrict__ kh,
                                                  char* __restrict__ kl) {
    int idx = blockIdx.x * blockDim.x + threadIdx.x;
    int i  = idx & 31;
    int s  = (idx >> 5) & (SS - 1);
    int bh = idx >> 16;

    float inv_freq = exp2f(-(float)i * (13.287712379549449f / 32.0f));
    float ang = (float)pos[s] * inv_freq;
    float c, sn;
    sincosf(ang, &sn, &c);

    size_t base = (((size_t)bh * SS) + s) * DK + 2 * i;

    float2 qv = *(const float2*)(Q + base);
    float2 kv = *(const float2*)(K + base);

    float q0 = (qv.x * c - qv.y * sn) * 0.125f;
    float q1 = (qv.x * sn + qv.y * c) * 0.125f;
    float k0 = kv.x * c - kv.y * sn;
    float k1 = kv.x * sn + kv.y * c;

    __nv_bfloat16 qh0 = __float2bfloat16(q0), qh1 = __float2bfloat16(q1);
    __nv_bfloat16 kh0 = __float2bfloat16(k0), kh1 = __float2bfloat16(k1);

    *(uint32_t*)(qh + base * 2) = pack_bf2(qh0, qh1);
    *(uint32_t*)(ql + base * 2) = pack_bf2(
        __float2bfloat16(q0 - __bfloat162float(qh0)),
        __float2bfloat16(q1 - __bfloat162float(qh1)));
    *(uint32_t*)(kh + base * 2) = pack_bf2(kh0, kh1);
    *(uint32_t*)(kl + base * 2) = pack_bf2(
        __float2bfloat16(k0 - __bfloat162float(kh0)),
        __float2bfloat16(k1 - __bfloat162float(kh1)));
}

// V fp32 [b,h,s,d] -> hi/lo bf16 planes
__global__ __launch_bounds__(256) void v_split(const float* __restrict__ V,
                                               char* __restrict__ vh,
                                               char* __restrict__ vl) {
    int idx = blockIdx.x * blockDim.x + threadIdx.x;
    int c  = idx & 15;
    int s  = (idx >> 4) & (SS - 1);
    int bh = idx >> 15;

    size_t base = (((size_t)bh * SS) + s) * DK + c * 4;
    float4 v = *(const float4*)(V + base);

    __nv_bfloat16 h0 = __float2bfloat16(v.x), h1 = __float2bfloat16(v.y);
    __nv_bfloat16 h2 = __float2bfloat16(v.z), h3 = __float2bfloat16(v.w);

    *(uint2*)(vh + base * 2) = make_uint2(pack_bf2(h0, h1), pack_bf2(h2, h3));
    *(uint2*)(vl + base * 2) = make_uint2(
        pack_bf2(__float2bfloat16(v.x - __bfloat162float(h0)),
                 __float2bfloat16(v.y - __bfloat162float(h1))),
        pack_bf2(__float2bfloat16(v.z - __bfloat162float(h2)),
                 __float2bfloat16(v.w - __bfloat162float(h3))));
}

// ---------------------------------------------------------------------------
// HMMA causal flash attention, bf16 hi/lo split (Q,K,P,V all split).
// CTA: 64 q-rows, 4 warps (one m16 tile each), K/V tiles of 64 keys,
// cp.async double-buffered. Writes O in [b,s,h*64+d] fp32.
// smem: Q(hi/lo) 16KB + 2 x (kh,kl,vh,vl each 8KB) = 80KB.
// ---------------------------------------------------------------------------
#define ATTN_SMEM 81920

__global__ __launch_bounds__(128) void attn_mma(const char* __restrict__ qhp,
                                                const char* __restrict__ qlp,
                                                const char* __restrict__ khp,
                                                const char* __restrict__ klp,
                                                const char* __restrict__ vhp,
                                                const char* __restrict__ vlp,
                                                float* __restrict__ O) {
    uint32_t sb = smem_u32(dsm);
    int tid = threadIdx.x, wid = tid >> 5, lane = tid & 31;
    int qt = blockIdx.x, h = blockIdx.y, b = blockIdx.z;
    size_t pbase = ((size_t)(b * N_HEADS + h)) * SS * 128;  // 128B per row

#define KVB(buf) (sb + 16384u + (uint32_t)(buf) * 32768u)
#define STAGE_KV(kt, buf)                                                  \
    do {                                                                   \
        size_t off = pbase + (size_t)(kt) * 64 * 128;                      \
        uint32_t kb = KVB(buf);                                            \
        _Pragma("unroll")                                                  \
        for (int i = 0; i < 4; i++) {                                      \
            int q = tid * 4 + i, r = q >> 3, c = q & 7;                    \
            uint32_t d = kb + r * 128 + ((c ^ (r & 7)) << 4);              \
            size_t g = off + r * 128 + c * 16;                             \
            CP16(d,         khp + g);                                      \
            CP16(d + 8192,  klp + g);                                      \
            CP16(d + 16384, vhp + g);                                      \
            CP16(d + 24576, vlp + g);                                      \
        }                                                                  \
    } while (0)

    // stage Q (hi/lo) + K/V tile 0
    {
        const char* qhg = qhp + pbase + (size_t)qt * 64 * 128;
        const char* qlg = qlp + pbase + (size_t)qt * 64 * 128;
#pragma unroll
        for (int i = 0; i < 4; i++) {
            int q = tid * 4 + i, r = q >> 3, c = q & 7;
            uint32_t d = sb + r * 128 + ((c ^ (r & 7)) << 4);
            CP16(d, qhg + r * 128 + c * 16);
            CP16(d + 8192, qlg + r * 128 + c * 16);
        }
    }
    STAGE_KV(0, 0);
    CPCOMMIT();
    CPWAIT0();
    __syncthreads();

    // persistent Q fragments (A-operand): 4 k-steps x 4 regs, hi & lo
    uint32_t qhf[4][4], qlf[4][4];
#pragma unroll
    for (int k = 0; k < 4; k++) {
        int row = wid * 16 + (lane & 15);
        int ch  = 2 * k + (lane >> 4);
        uint32_t a = sb + row * 128 + ((ch ^ (row & 7)) << 4);
        ldsm4(qhf[k], a);
        ldsm4(qlf[k], a + 8192);
    }

    float oacc[8][4];
#pragma unroll
    for (int nt = 0; nt < 8; nt++)
#pragma unroll
        for (int j = 0; j < 4; j++) oacc[nt][j] = 0.f;
    float m1 = -1e30f, m2 = -1e30f, l1 = 0.f, l2 = 0.f;
    int rl1 = wid * 16 + (lane >> 2), rl2 = rl1 + 8;  // local rows (0..63)

    for (int kt = 0; kt <= qt; kt++) {
        int buf = kt & 1;
        if (kt < qt) {
            STAGE_KV(kt + 1, buf ^ 1);
            CPCOMMIT();
        }
        uint32_t base = KVB(buf);

        // ---- S = Q K^T (hi/lo x3) ----
        float sacc[8][4];
#pragma unroll
        for (int nt = 0; nt < 8; nt++)
#pragma unroll
            for (int j = 0; j < 4; j++) sacc[nt][j] = 0.f;

#pragma unroll
        for (int p = 0; p < 4; p++) {
#pragma unroll
            for (int k = 0; k < 4; k++) {
                int row = p * 16 + (lane & 7) + ((lane >> 4) << 3);
                int ch  = 2 * k + ((lane >> 3) & 1);
                uint32_t a = base + row * 128 + ((ch ^ (row & 7)) << 4);
                uint32_t kh4[4], kl4[4];
                ldsm4(kh4, a);
                ldsm4(kl4, a + 8192);
                mma_bf16(sacc[2 * p],     qhf[k], kh4[0], kh4[1]);
                mma_bf16(sacc[2 * p],     qhf[k], kl4[0], kl4[1]);
                mma_bf16(sacc[2 * p],     qlf[k], kh4[0], kh4[1]);
                mma_bf16(sacc[2 * p + 1], qhf[k], kh4[2], kh4[3]);
                mma_bf16(sacc[2 * p + 1], qhf[k], kl4[2], kl4[3]);
                mma_bf16(sacc[2 * p + 1], qlf[k], kh4[2], kh4[3]);
            }
        }

        // ---- causal mask (diagonal tile only) ----
        if (kt == qt) {
#pragma unroll
            for (int nt = 0; nt < 8; nt++) {
                int cl = nt * 8 + (lane & 3) * 2;
                if (cl > rl1)     sacc[nt][0] = -1e30f;
                if (cl + 1 > rl1) sacc[nt][1] = -1e30f;
                if (cl > rl2)     sacc[nt][2] = -1e30f;
                if (cl + 1 > rl2) sacc[nt][3] = -1e30f;
            }
        }

        // ---- online softmax ----
        float tm1 = -1e30f, tm2 = -1e30f;
#pragma unroll
        for (int nt = 0; nt < 8; nt++) {
            tm1 = fmaxf(tm1, fmaxf(sacc[nt][0], sacc[nt][1]));
            tm2 = fmaxf(tm2, fmaxf(sacc[nt][2], sacc[nt][3]));
        }
        tm1 = fmaxf(tm1, __shfl_xor_sync(0xffffffffu, tm1, 1));
        tm1 = fmaxf(tm1, __shfl_xor_sync(0xffffffffu, tm1, 2));
        tm2 = fmaxf(tm2, __shfl_xor_sync(0xffffffffu, tm2, 1));
        tm2 = fmaxf(tm2, __shfl_xor_sync(0xffffffffu, tm2, 2));

        float nm1 = fmaxf(m1, tm1), nm2 = fmaxf(m2, tm2);
        float c1 = __expf(m1 - nm1), c2 = __expf(m2 - nm2);
        l1 *= c1;
        l2 *= c2;
#pragma unroll
        for (int nt = 0; nt < 8; nt++) {
            oacc[nt][0] *= c1;
            oacc[nt][1] *= c1;
            oacc[nt][2] *= c2;
            oacc[nt][3] *= c2;
        }
        m1 = nm1;
        m2 = nm2;

        uint32_t phf[4][4], plf[4][4];
#pragma unroll
        for (int p = 0; p < 4; p++) {
            float e0 = __expf(sacc[2 * p][0] - nm1);
            float e1 = __expf(sacc[2 * p][1] - nm1);
            float e2 = __expf(sacc[2 * p][2] - nm2);
            float e3 = __expf(sacc[2 * p][3] - nm2);
            float e4 = __expf(sacc[2 * p + 1][0] - nm1);
            float e5 = __expf(sacc[2 * p + 1][1] - nm1);
            float e6 = __expf(sacc[2 * p + 1][2] - nm2);
            float e7 = __expf(sacc[2 * p + 1][3] - nm2);
            l1 += e0 + e1 + e4 + e5;
            l2 += e2 + e3 + e6 + e7;
            __nv_bfloat16 h0 = __float2bfloat16(e0), h1 = __float2bfloat16(e1);
            __nv_bfloat16 h2 = __float2bfloat16(e2), h3 = __float2bfloat16(e3);
            __nv_bfloat16 h4 = __float2bfloat16(e4), h5 = __float2bfloat16(e5);
            __nv_bfloat16 h6 = __float2bfloat16(e6), h7 = __float2bfloat16(e7);
            phf[p][0] = pack_bf2(h0, h1);
            phf[p][1] = pack_bf2(h2, h3);
            phf[p][2] = pack_bf2(h4, h5);
            phf[p][3] = pack_bf2(h6, h7);
            plf[p][0] = pack_bf2(__float2bfloat16(e0 - __bfloat162float(h0)),
                                 __float2bfloat16(e1 - __bfloat162float(h1)));
            plf[p][1] = pack_bf2(__float2bfloat16(e2 - __bfloat162float(h2)),
                                 __float2bfloat16(e3 - __bfloat162float(h3)));
            plf[p][2] = pack_bf2(__float2bfloat16(e4 - __bfloat162float(h4)),
                                 __float2bfloat16(e5 - __bfloat162float(h5)));
            plf[p][3] = pack_bf2(__float2bfloat16(e6 - __bfloat162float(h6)),
                                 __float2bfloat16(e7 - __bfloat162float(h7)));
        }

        // ---- O += P V (hi/lo x3) ----
#pragma unroll
        for (int dp = 0; dp < 4; dp++) {
#pragma unroll
            for (int k = 0; k < 4; k++) {
                int row = k * 16 + (lane & 7) + (((lane >> 3) & 1) << 3);
                int ch  = 2 * dp + (lane >> 4);
                uint32_t a = base + 16384 + row * 128 + ((ch ^ (row & 7)) << 4);
                uint32_t vh4[4], vl4[4];
                ldsm4t(vh4, a);
                ldsm4t(vl4, a + 8192);
                mma_bf16(oacc[2 * dp],     phf[k], vh4[0], vh4[1]);
                mma_bf16(oacc[2 * dp],     phf[k], vl4[0], vl4[1]);
                mma_bf16(oacc[2 * dp],     plf[k], vh4[0], vh4[1]);
                mma_bf16(oacc[2 * dp + 1], phf[k], vh4[2], vh4[3]);
                mma_bf16(oacc[2 * dp + 1], phf[k], vl4[2], vl4[3]);
                mma_bf16(oacc[2 * dp + 1], plf[k], vh4[2], vh4[3]);
            }
        }

        if (kt < qt) {
            CPWAIT0();
            __syncthreads();
        }
    }

    // ---- epilogue ----
    l1 += __shfl_xor_sync(0xffffffffu, l1, 1);
    l1 += __shfl_xor_sync(0xffffffffu, l1, 2);
    l2 += __shfl_xor_sync(0xffffffffu, l2, 1);
    l2 += __shfl_xor_sync(0xffffffffu, l2, 2);
    float i1 = 1.f / l1, i2 = 1.f / l2;

    int r1g = qt * 64 + rl1, r2g = qt * 64 + rl2;
    float* o1 = O + ((size_t)(b * SS + r1g)) * D_MODEL + h * DK + (lane & 3) * 2;
    float* o2 = O + ((size_t)(b * SS + r2g)) * D_MODEL + h * DK + (lane & 3) * 2;
#pragma unroll
    for (int nt = 0; nt < 8; nt++) {
        *(float2*)(o1 + nt * 8) = make_float2(oacc[nt][0] * i1, oacc[nt][1] * i1);
        *(float2*)(o2 + nt * 8) = make_float2(oacc[nt][2] * i2, oacc[nt][3] * i2);
    }
#undef STAGE_KV
#undef KVB
}

// ---------------------------------------------------------------------------
extern "C" void kernel_launch(void* const* d_in, const int* in_sizes, int n_in,
                              void* d_out, int out_size) {
    const float* x   = (const float*)d_in[0];
    const int*   pos = (const int*)d_in[1];
    const float* WQ  = (const float*)d_in[2];
    const float* WK  = (const float*)d_in[3];
    const float* WV  = (const float*)d_in[4];
    const float* WO  = (const float*)d_in[5];
    float* out = (float*)d_out;

    float *Qb, *Kb, *Vb, *Ob;
    char *xc, *wc, *qh, *ql, *kh, *kl, *vh, *vl;
    cudaGetSymbolAddress((void**)&Qb, g_Q);
    cudaGetSymbolAddress((void**)&Kb, g_K);
    cudaGetSymbolAddress((void**)&Vb, g_V);
    cudaGetSymbolAddress((void**)&Ob, g_O);
    cudaGetSymbolAddress((void**)&xc, g_xc);
    cudaGetSymbolAddress((void**)&wc, g_wc);
    cudaGetSymbolAddress((void**)&qh, g_qh);
    cudaGetSymbolAddress((void**)&ql, g_ql);
    cudaGetSymbolAddress((void**)&kh, g_kh);
    cudaGetSymbolAddress((void**)&kl, g_kl);
    cudaGetSymbolAddress((void**)&vh, g_vh);
    cudaGetSymbolAddress((void**)&vl, g_vl);

    cudaFuncSetAttribute(gemm_hmma, cudaFuncAttributeMaxDynamicSharedMemorySize, 65536);
    cudaFuncSetAttribute(attn_mma, cudaFuncAttributeMaxDynamicSharedMemorySize, ATTN_SMEM);

    dim3 ggrid(D_MODEL / 128, M_TOT / 128); // (8, 64)

    // QKV projections
    convert_split<<<(M_TOT * 32) / 256, 256>>>(x, xc, 13);
    convert_split<<<(1024 * 32) / 256, 256>>>(WQ, wc, 10);
    gemm_hmma<<<ggrid, 256, 65536>>>(xc, wc, Qb, 1);
    convert_split<<<(1024 * 32) / 256, 256>>>(WK, wc, 10);
    gemm_hmma<<<ggrid, 256, 65536>>>(xc, wc, Kb, 1);
    convert_split<<<(1024 * 32) / 256, 256>>>(WV, wc, 10);
    gemm_hmma<<<ggrid, 256, 65536>>>(xc, wc, Vb, 1);

    // RoPE + split conversion
    rope_split<<<(BB * N_HEADS * SS * 32) / 256, 256>>>(Qb, Kb, pos, qh, ql, kh, kl);
    v_split<<<(BB * N_HEADS * SS * 16) / 256, 256>>>(Vb, vh, vl);

    // HMMA flash attention
    attn_mma<<<dim3(SS / 64, N_HEADS, BB), 128, ATTN_SMEM>>>(qh, ql, kh, kl, vh, vl, Ob);

    // output projection
    convert_split<<<(M_TOT * 32) / 256, 256>>>(Ob, xc, 13);
    convert_split<<<(1024 * 32) / 256, 256>>>(WO, wc, 10);
    gemm_hmma<<<ggrid, 256, 65536>>>(xc, wc, out, 0);
}